// round 11
// baseline (speedup 1.0000x reference)
#include <cuda_runtime.h>
#include <cuda_bf16.h>

// Output: [Cm1, 1, R, 85] fp32 flat (NC=81). Specialized one-pass kernel:
// every output byte written exactly once; each thread serves 8 class planes
// from registers (cls loaded once, multicast via 8 streaming stores).
//
// Group structure: 4 rows = 340 elements = exactly 85 float4s.
// Boundary float4 positions (touch box slots): {20,21,41,42,62,63,84} -> slow.
// Fast remap: w in [0,78) -> p = w + 2*cnt, cnt = (w>=20)+(w>=39)+(w>=58);
//             row = 4g + cnt; cls float4 idx = 81g + w + cnt.

#define CGRP 8   // classes per blockIdx.y

__global__ void __launch_bounds__(256)
bb_mc_kernel(const float* __restrict__ cls,     // [R, 81]
             const float4* __restrict__ cls4,
             const float4* __restrict__ regr4,  // [R, Cm1] of float4
             const float4* __restrict__ rois,   // [R] of float4
             float4* __restrict__ out4,
             int perC4,        // 85*R/4
             int R, int Cm1,
             int fastBlocks,   // blocks covering 78*(R/4) fast threads
             int fastCount,    // 78*(R/4)
             int slowCount,    // 7*(R/4)
             float invW, float invH)
{
    const int cbase = blockIdx.y * CGRP;

    if (blockIdx.x < (unsigned)fastBlocks) {
        // ---------- FAST: 1 cls load -> CGRP streaming stores ----------
        int tf = blockIdx.x * 256 + threadIdx.x;
        if (tf >= fastCount) return;
        unsigned w = (unsigned)tf % 78u;
        unsigned g = (unsigned)tf / 78u;
        unsigned cnt = (w >= 20u) + (w >= 39u) + (w >= 58u);
        int t   = (int)(85u * g + w + 2u * cnt);      // float4 index in plane
        int idx = (int)(81u * g + w + cnt);           // float4 index in cls

        float4 v = __ldg(&cls4[idx]);
        float4* dst = out4 + (size_t)cbase * (size_t)perC4 + (size_t)t;
#pragma unroll
        for (int cc = 0; cc < CGRP; ++cc) {
            if (cbase + cc < Cm1) __stcs(dst, v);
            dst += perC4;
        }
        return;
    }

    // ---------- SLOW: boundary float4s (contain box elements) ----------
    int u = (blockIdx.x - fastBlocks) * 256 + threadIdx.x;
    if (u >= slowCount) return;
    unsigned q = (unsigned)u % 7u;
    unsigned g = (unsigned)u / 7u;
    unsigned p = (q == 6u) ? 84u : (20u + 21u * (q >> 1) + (q & 1u));
    int t = (int)(85u * g + p);

    unsigned rem0 = (unsigned)t << 2;
    unsigned r  = rem0 / 85u;
    unsigned k0 = rem0 - r * 85u;

    float4 roi = __ldg(&rois[r]);                     // x, y, w, h (c-invariant)

    // Class-invariant per-lane blend setup: cls scalar or box component id.
    float clsv[4];
    int   comp[4];                                    // -1 => cls, else 0..3
#pragma unroll
    for (int i = 0; i < 4; ++i) {
        int k = (int)k0 + i;
        int rr = (int)r;
        if (k >= 85) { k -= 85; ++rr; }               // wrap to next row's cls
        if (k < 81) { comp[i] = -1; clsv[i] = __ldg(&cls[(size_t)rr * 81 + k]); }
        else        { comp[i] = k - 81; clsv[i] = 0.0f; }
    }

    float4* dst = out4 + (size_t)cbase * (size_t)perC4 + (size_t)t;
#pragma unroll
    for (int cc = 0; cc < CGRP; ++cc) {
        int c = cbase + cc;
        if (c < Cm1) {
            float4 tg = __ldg(&regr4[(size_t)r * Cm1 + c]);  // tx,ty,tw,th
            float gx = rintf(fmaf(roi.z, tg.x, roi.x));
            float gy = rintf(fmaf(roi.w, tg.y, roi.y));
            float gw = rintf(roi.z * expf(tg.z));
            float gh = rintf(roi.w * expf(tg.w));
            float b0 = gx * invW;
            float b1 = gy * invH;
            float b2 = (gx + gw) * invW;
            float b3 = (gy + gh) * invH;

            float v[4];
#pragma unroll
            for (int i = 0; i < 4; ++i) {
                float bv = (comp[i] == 0) ? b0 :
                           (comp[i] == 1) ? b1 :
                           (comp[i] == 2) ? b2 : b3;
                v[i] = (comp[i] < 0) ? clsv[i] : bv;
            }
            float4 o; o.x = v[0]; o.y = v[1]; o.z = v[2]; o.w = v[3];
            __stcs(dst, o);
        }
        dst += perC4;
    }
}

// ---------------- Proven R9 two-pass fallback (odd shapes) ----------------
__global__ void __launch_bounds__(256)
cls_broadcast_kernel(const float4* __restrict__ cls4, float4* __restrict__ out4,
                     int perC4, int rowlen, int maxClsIdx)
{
    int t = blockIdx.x * 256 + threadIdx.x;
    if (t >= perC4) return;
    const int c = blockIdx.y;
    unsigned rem0 = (unsigned)t << 2;
    unsigned r  = rem0 / (unsigned)rowlen;
    unsigned k0 = rem0 - r * (unsigned)rowlen;
    unsigned rr = r + (k0 >= (unsigned)(rowlen - 3));
    int idx = t - (int)rr;
    idx = min(idx, maxClsIdx);
    out4[(size_t)c * (size_t)perC4 + (size_t)t] = __ldg(&cls4[idx]);
}

__global__ void __launch_bounds__(256)
box_kernel_v2(const float4* __restrict__ regr4, const float4* __restrict__ rois,
              float* __restrict__ out, int R, int Cm1, int NC,
              float invW, float invH)
{
    int u = blockIdx.x * 256 + threadIdx.x;
    if (u >= 4 * R) return;
    const int c = blockIdx.y;
    const int r = u >> 2;
    const int j = u & 3;
    float4 roi = __ldg(&rois[r]);
    float4 tg  = __ldg(&regr4[(size_t)r * Cm1 + c]);
    const bool odd = (j & 1);
    const bool hi  = (j >= 2);
    float s   = odd ? roi.w : roi.z;
    float o   = odd ? roi.y : roi.x;
    float inv = odd ? invH  : invW;
    float t1  = odd ? tg.y  : tg.x;
    float t2  = odd ? tg.w  : tg.z;
    float base  = rintf(fmaf(s, t1, o));
    float extra = rintf(s * expf(t2));
    float val   = (base + (hi ? extra : 0.0f)) * inv;
    out[((size_t)c * R + r) * (size_t)(NC + 4) + NC + j] = val;
}

__global__ void __launch_bounds__(256)
bb_generic_kernel(const float* __restrict__ regr, const float* __restrict__ cls,
                  const float4* __restrict__ rois, float* __restrict__ out,
                  int R, int Cm1, int NC, float invW, float invH, long long total)
{
    long long idx = (long long)blockIdx.x * blockDim.x + threadIdx.x;
    long long stride = (long long)gridDim.x * blockDim.x;
    const int rowlen = NC + 4;
    const long long perC = (long long)R * rowlen;
    for (; idx < total; idx += stride) {
        int c   = (int)(idx / perC);
        int rem = (int)(idx - (long long)c * perC);
        int r   = rem / rowlen;
        int k   = rem - r * rowlen;
        float val;
        if (k < NC) {
            val = cls[(long long)r * NC + k];
        } else {
            float4 roi = __ldg(&rois[r]);
            const float* rg = regr + ((long long)r * Cm1 + c) * 4;
            int comp = k - NC;
            if (comp == 0)      val = rintf(fmaf(roi.z, rg[0], roi.x)) * invW;
            else if (comp == 1) val = rintf(fmaf(roi.w, rg[1], roi.y)) * invH;
            else if (comp == 2) val = (rintf(fmaf(roi.z, rg[0], roi.x)) +
                                       rintf(roi.z * expf(rg[2]))) * invW;
            else                val = (rintf(fmaf(roi.w, rg[1], roi.y)) +
                                       rintf(roi.w * expf(rg[3]))) * invH;
        }
        out[idx] = val;
    }
}

extern "C" void kernel_launch(void* const* d_in, const int* in_sizes, int n_in,
                              void* d_out, int out_size)
{
    const float*  regr = (const float*)d_in[0];   // [1, R, 4*Cm1]
    const float*  cls  = (const float*)d_in[1];   // [1, R, NC]
    const float4* rois = (const float4*)d_in[2];  // [1, R, 4]

    const int R   = in_sizes[2] / 4;
    const int Cm1 = in_sizes[0] / (R * 4);
    const int NC  = in_sizes[1] / R;
    const int rowlen = NC + 4;

    long long hw = (long long)in_sizes[3] / 3;    // H = W = isqrt(b_elems/3)
    int side = 1;
    while ((long long)(side + 1) * (side + 1) <= hw) ++side;
    const float invW = 1.0f / (float)side;
    const float invH = 1.0f / (float)side;

    float* out = (float*)d_out;
    const long long perC  = (long long)R * rowlen;
    const long long total = (long long)out_size;

    if (rowlen == 85 && (R % 4) == 0 &&
        total == (long long)Cm1 * perC && (perC % 4) == 0) {
        const int perC4     = (int)(perC >> 2);
        const int groups    = R / 4;
        const int fastCount = 78 * groups;
        const int slowCount = 7 * groups;
        const int fastBlocks = (fastCount + 255) / 256;
        const int slowBlocks = (slowCount + 255) / 256;
        dim3 grid(fastBlocks + slowBlocks, (Cm1 + CGRP - 1) / CGRP);
        bb_mc_kernel<<<grid, 256>>>(
            cls, (const float4*)cls, (const float4*)regr, rois,
            (float4*)out, perC4, R, Cm1,
            fastBlocks, fastCount, slowCount, invW, invH);
    } else if ((perC % 4) == 0 && (((long long)R * NC) % 4) == 0 &&
               total == (long long)Cm1 * perC) {
        const int perC4 = (int)(perC >> 2);
        const int maxClsIdx = (int)(((long long)R * NC - 4) >> 2);
        dim3 gridA((perC4 + 255) / 256, Cm1);
        cls_broadcast_kernel<<<gridA, 256>>>(
            (const float4*)cls, (float4*)out, perC4, rowlen, maxClsIdx);
        dim3 gridB((4 * R + 255) / 256, Cm1);
        box_kernel_v2<<<gridB, 256>>>(
            (const float4*)regr, rois, out, R, Cm1, NC, invW, invH);
    } else {
        long long blocks = (total + 255) / 256;
        if (blocks > 262144) blocks = 262144;
        bb_generic_kernel<<<(unsigned)blocks, 256>>>(
            regr, cls, rois, out, R, Cm1, NC, invW, invH, total);
    }
}